// round 15
// baseline (speedup 1.0000x reference)
#include <cuda_runtime.h>
#include <cuda_bf16.h>
#include <math.h>
#include <stdint.h>

#define ETHREADS 256
#define NTHREADS 256
#define M_TILE 128
#define N_MAX 50000

#define STRIDE128 272
#define STRIDE64  144

// ---- padded bf16 weight images ----
#define IWCB 0        // Wcomb [128x128] s272 : 34816
#define IWE2 34816    // We2   [128x128] s272 : 34816
#define IWC  69632    // Wc    [128x64]  s144 : 18432
#define IMG_TOTAL 88064
__device__ __align__(16) unsigned char g_wimg[IMG_TOTAL];

// per-node m1 table: Y1 = relu(h@Wn1+b1)@Wn2, bf16 [N_MAX x 128]
__device__ __align__(16) __nv_bfloat16 g_Y1[(size_t)N_MAX * 128];

// dynamic tile ticket (reset by cudaMemsetAsync each launch)
__device__ int g_ticket;

// ---- edge kernel smem (bytes) — SX eliminated (in-place in SA) ----
#define WBUF_OFF 0          // 34816 streamed weight
#define SA_OFF   34816      // 34816 A = [t|eh] -> x2 -> p (in place)
#define SB2_OFF  69632      // 512
#define SSRC_OFF 70144      // 512
#define SDST_OFF 70656      // 512
#define STILE_OFF 71168     // 16
#define ESMEM_BYTES 71184   // x3 CTAs = 213552 < 227KB

// ---- node kernel smem ----
#define NW1_OFF 0
#define NW2_OFF (NW1_OFF + 64*STRIDE128)
#define NH_OFF  (NW2_OFF + 128*STRIDE128)
#define NX_OFF  (NH_OFF + 128*STRIDE64)
#define NB_OFF  (NX_OFF + 128*STRIDE128)
#define NSMEM_BYTES (NB_OFF + 512)

__device__ __forceinline__ uint32_t smem_u32(const void* p) {
    uint32_t a;
    asm("{ .reg .u64 t; cvta.to.shared.u64 t, %1; cvt.u32.u64 %0, t; }" : "=r"(a) : "l"(p));
    return a;
}
__device__ __forceinline__ uint32_t pack2_bf16(float a, float b) {
    __nv_bfloat162 p = __float22bfloat162_rn(make_float2(a, b));
    return *(unsigned int*)&p;
}
__device__ __forceinline__ uint2 pack4_bf16(float a, float b, float c, float d) {
    uint2 r; r.x = pack2_bf16(a, b); r.y = pack2_bf16(c, d); return r;
}
__device__ __forceinline__ float fast_tanh(float x) {
    float y;
    asm("tanh.approx.f32 %0, %1;" : "=f"(y) : "f"(x));
    return y;
}
__device__ __forceinline__ void ldsm_x4(uint32_t addr, uint32_t r[4]) {
    asm volatile("ldmatrix.sync.aligned.m8n8.x4.shared.b16 {%0,%1,%2,%3}, [%4];"
        : "=r"(r[0]), "=r"(r[1]), "=r"(r[2]), "=r"(r[3]) : "r"(addr));
}
__device__ __forceinline__ void ldsm_x4t(uint32_t addr, uint32_t r[4]) {
    asm volatile("ldmatrix.sync.aligned.m8n8.x4.trans.shared.b16 {%0,%1,%2,%3}, [%4];"
        : "=r"(r[0]), "=r"(r[1]), "=r"(r[2]), "=r"(r[3]) : "r"(addr));
}
__device__ __forceinline__ void mma16816(float d[4], const uint32_t a[4], const uint32_t b[2]) {
    asm volatile("mma.sync.aligned.m16n8k16.row.col.f32.bf16.bf16.f32 "
        "{%0,%1,%2,%3},{%4,%5,%6,%7},{%8,%9},{%0,%1,%2,%3};"
        : "+f"(d[0]), "+f"(d[1]), "+f"(d[2]), "+f"(d[3])
        : "r"(a[0]), "r"(a[1]), "r"(a[2]), "r"(a[3]), "r"(b[0]), "r"(b[1]));
}

// cp.async weight stream
__device__ __forceinline__ void cp_w(uint32_t sdst, int img_off, int bytes, int tid) {
    const unsigned char* gsrc = g_wimg + img_off;
    for (int i = tid * 16; i < bytes; i += ETHREADS * 16)
        asm volatile("cp.async.cg.shared.global [%0], [%1], 16;"
                     :: "r"(sdst + i), "l"(gsrc + i));
    asm volatile("cp.async.commit_group;");
}
#define CP_WAIT0() asm volatile("cp.async.wait_group 0;" ::: "memory")

// warp covers 64 rows (2 halves x 2 m16 tiles), B frags reused across halves
template<int KT, int NTH>
__device__ __forceinline__ void mma_stage2(uint32_t aAddr, int aStride,
                                           uint32_t wAddr, int wStride,
                                           int m0, int n0, int lane,
                                           float acc[2][2][NTH][4]) {
#pragma unroll
    for (int hf = 0; hf < 2; ++hf)
#pragma unroll
        for (int mt = 0; mt < 2; ++mt)
#pragma unroll
            for (int n = 0; n < NTH; ++n)
#pragma unroll
                for (int e = 0; e < 4; ++e) acc[hf][mt][n][e] = 0.f;
    const int krow = lane & 15;
    const int xoff = (lane >> 4) << 3;
#pragma unroll
    for (int k = 0; k < KT; ++k) {
        uint32_t b[NTH / 2][4];
#pragma unroll
        for (int np = 0; np < NTH / 2; ++np)
            ldsm_x4t(wAddr + (uint32_t)(k * 16 + krow) * wStride + (uint32_t)(n0 + np * 16 + xoff) * 2, b[np]);
#pragma unroll
        for (int hf = 0; hf < 2; ++hf) {
            uint32_t a[2][4];
#pragma unroll
            for (int mt = 0; mt < 2; ++mt)
                ldsm_x4(aAddr + (uint32_t)(m0 + hf * 32 + mt * 16 + krow) * aStride + (uint32_t)(k * 16 + xoff) * 2, a[mt]);
#pragma unroll
            for (int np = 0; np < NTH / 2; ++np) {
                mma16816(acc[hf][0][np * 2 + 0], a[0], b[np] + 0);
                mma16816(acc[hf][1][np * 2 + 0], a[1], b[np] + 0);
                mma16816(acc[hf][0][np * 2 + 1], a[0], b[np] + 2);
                mma16816(acc[hf][1][np * 2 + 1], a[1], b[np] + 2);
            }
        }
    }
}

// single-strip version: warp covers 32 rows (2 m16 tiles) x NTH*8 cols
template<int KT, int NTH>
__device__ __forceinline__ void mma_stage(uint32_t aAddr, int aStride,
                                          uint32_t wAddr, int wStride,
                                          int m0, int n0, int lane,
                                          float acc[2][NTH][4]) {
#pragma unroll
    for (int mt = 0; mt < 2; ++mt)
#pragma unroll
        for (int n = 0; n < NTH; ++n)
#pragma unroll
            for (int e = 0; e < 4; ++e) acc[mt][n][e] = 0.f;
    const int krow = lane & 15;
    const int xoff = (lane >> 4) << 3;
#pragma unroll
    for (int k = 0; k < KT; ++k) {
        uint32_t a[2][4];
#pragma unroll
        for (int mt = 0; mt < 2; ++mt)
            ldsm_x4(aAddr + (uint32_t)(m0 + mt * 16 + krow) * aStride + (uint32_t)(k * 16 + xoff) * 2, a[mt]);
#pragma unroll
        for (int np = 0; np < NTH / 2; ++np) {
            uint32_t b[4];
            ldsm_x4t(wAddr + (uint32_t)(k * 16 + krow) * wStride + (uint32_t)(n0 + np * 16 + xoff) * 2, b);
            mma16816(acc[0][np * 2 + 0], a[0], b + 0);
            mma16816(acc[1][np * 2 + 0], a[1], b + 0);
            mma16816(acc[0][np * 2 + 1], a[0], b + 2);
            mma16816(acc[1][np * 2 + 1], a[1], b + 2);
        }
    }
}

__device__ __forceinline__ void load_weight_smem(char* smemc, int off, const float* __restrict__ W,
                                                 int K, int N, int stride, int tid, int nthr) {
    int n4 = (K * N) >> 2;
    for (int i = tid; i < n4; i += nthr) {
        int idx = i << 2;
        int r = idx / N, c = idx % N;
        float4 v = *(const float4*)(W + idx);
        *(uint2*)(smemc + off + r * stride + c * 2) = pack4_bf16(v.x, v.y, v.z, v.w);
    }
}

// =============== node kernel: Y1 table + residual init + weight conversion ===============
__global__ __launch_bounds__(NTHREADS)
void node_kernel(const float* __restrict__ h,
                 const float* __restrict__ Wn1, const float* __restrict__ bn1,
                 const float* __restrict__ Wn2,
                 const float* __restrict__ Wue, const float* __restrict__ We1,
                 const float* __restrict__ We2, const float* __restrict__ Wc,
                 float* __restrict__ out, int Nn, int nNodeBlocks)
{
    if (blockIdx.x >= nNodeBlocks) {
        int i = (blockIdx.x - nNodeBlocks) * NTHREADS + threadIdx.x;
        if (i < 16384) {                // Wcomb = [[0.2*Wue@We1],[0.8*We1]]
            int r = i >> 7, c = i & 127;
            float v;
            if (r < 64) {
                float s = 0.f;
#pragma unroll 8
                for (int k = 0; k < 64; ++k) s += Wue[r * 64 + k] * We1[k * 128 + c];
                v = 0.2f * s;
            } else {
                v = 0.8f * We1[(r - 64) * 128 + c];
            }
            *(__nv_bfloat16*)(g_wimg + IWCB + r * STRIDE128 + c * 2) = __float2bfloat16(v);
        } else if (i < 32768) {         // We2
            int j = i - 16384, r = j >> 7, c = j & 127;
            *(__nv_bfloat16*)(g_wimg + IWE2 + r * STRIDE128 + c * 2) = __float2bfloat16(We2[j]);
        } else if (i < 40960) {         // Wc
            int j = i - 32768, r = j >> 6, c = j & 63;
            *(__nv_bfloat16*)(g_wimg + IWC + r * STRIDE64 + c * 2) = __float2bfloat16(Wc[j]);
        }
        return;
    }

    extern __shared__ char smem[];
    const uint32_t sbase = smem_u32(smem);
    const int tid = threadIdx.x;
    const int warp = tid >> 5;
    const int lane = tid & 31;
    const int mi = warp >> 1, nj = warp & 1;
    const int m0 = mi * 32, n0 = nj * 64;
    const int g = lane >> 2, q = lane & 3;
    const int r0 = blockIdx.x * 128;

    float* sB = (float*)(smem + NB_OFF);
    load_weight_smem(smem, NW1_OFF, Wn1, 64, 128, STRIDE128, tid, NTHREADS);
    load_weight_smem(smem, NW2_OFF, Wn2, 128, 128, STRIDE128, tid, NTHREADS);
    if (tid < 128) sB[tid] = bn1[tid];

    for (int i = tid; i < 128 * 16; i += NTHREADS) {
        int r = i >> 4, d4 = i & 15;
        int nr = r0 + r;
        bool valid = (nr < Nn);
        if (!valid) nr = Nn - 1;
        float4 v = ((const float4*)(h + (size_t)nr * 64))[d4];
        if (valid) ((float4*)(out + (size_t)nr * 64))[d4] = v;
        *(uint2*)(smem + NH_OFF + r * STRIDE64 + d4 * 8) = pack4_bf16(v.x, v.y, v.z, v.w);
    }
    __syncthreads();

    float acc[2][8][4];
    mma_stage<4, 8>(sbase + NH_OFF, STRIDE64, sbase + NW1_OFF, STRIDE128, m0, n0, lane, acc);
#pragma unroll
    for (int mt = 0; mt < 2; ++mt)
#pragma unroll
        for (int n = 0; n < 8; ++n) {
            int col = n0 + n * 8 + q * 2;
            float b0 = sB[col], b1 = sB[col + 1];
            int rA = m0 + mt * 16 + g;
            *(uint32_t*)(smem + NX_OFF + rA * STRIDE128 + col * 2) =
                pack2_bf16(fmaxf(acc[mt][n][0] + b0, 0.f), fmaxf(acc[mt][n][1] + b1, 0.f));
            *(uint32_t*)(smem + NX_OFF + (rA + 8) * STRIDE128 + col * 2) =
                pack2_bf16(fmaxf(acc[mt][n][2] + b0, 0.f), fmaxf(acc[mt][n][3] + b1, 0.f));
        }
    __syncthreads();

    mma_stage<8, 8>(sbase + NX_OFF, STRIDE128, sbase + NW2_OFF, STRIDE128, m0, n0, lane, acc);
#pragma unroll
    for (int mt = 0; mt < 2; ++mt)
#pragma unroll
        for (int n = 0; n < 8; ++n) {
            int col = n0 + n * 8 + q * 2;
            int rA = m0 + mt * 16 + g;
            int nrA = r0 + rA, nrB = r0 + rA + 8;
            if (nrA < Nn)
                *(uint32_t*)(g_Y1 + (size_t)nrA * 128 + col) = pack2_bf16(acc[mt][n][0], acc[mt][n][1]);
            if (nrB < Nn)
                *(uint32_t*)(g_Y1 + (size_t)nrB * 128 + col) = pack2_bf16(acc[mt][n][2], acc[mt][n][3]);
        }
}

// =============== edge kernel: 3 CTAs/SM, in-place activations, dynamic tiles ===============
__global__ __launch_bounds__(ETHREADS, 3)
void edge_kernel(const float* __restrict__ h, const float* __restrict__ eh,
                 const float* __restrict__ be1,
                 const int* __restrict__ src, const int* __restrict__ dst,
                 float* __restrict__ out, int E, int nTiles)
{
    extern __shared__ char smem[];
    const uint32_t sbase = smem_u32(smem);
    const int tid = threadIdx.x;
    const int warp = tid >> 5;
    const int lane = tid & 31;

    // stages A/B: 2 M-strips (64 rows) x 4 N-quarters
    const int mi = warp >> 2;
    const int nj = warp & 3;
    const int m0 = mi * 64;
    const int n0w = nj * 32;   // N=128 (NTH=4)
    // stage C remap: 4 M-strips (32 rows) x 2 N-halves
    const int m0c = (warp & 3) * 32;
    const int n0c = (warp >> 2) * 32;
    const int g = lane >> 2, q = lane & 3;

    float* sB2 = (float*)(smem + SB2_OFF);
    int* sSrc = (int*)(smem + SSRC_OFF);
    int* sDst = (int*)(smem + SDST_OFF);
    int* sTile = (int*)(smem + STILE_OFF);

    if (tid < 128) sB2[tid] = be1[tid];

    // prologue: first ticket + first Wcomb stream
    if (tid == 0) sTile[0] = atomicAdd(&g_ticket, 1);
    cp_w(sbase + WBUF_OFF, IWCB, 34816, tid);
    __syncthreads();
    int tile = sTile[0];

    while (tile < nTiles) {
        const int e0 = tile * M_TILE;

        // idx -> smem + gather with direct broadcast LDG
        if (tid < M_TILE) {
            int eg = e0 + tid; if (eg >= E) eg = E - 1;
            sSrc[tid] = src[eg];
            sDst[tid] = dst[eg];
        }
#pragma unroll
        for (int c = 0; c < 2; ++c) {
            int ss[4], dd[4];
            float4 va[4], vb[4], ve[4];
#pragma unroll
            for (int j = 0; j < 4; ++j) {
                int i = tid + (c * 4 + j) * ETHREADS;
                int e = i >> 4;
                int eg = e0 + e; if (eg >= E) eg = E - 1;
                ss[j] = src[eg]; dd[j] = dst[eg];
            }
#pragma unroll
            for (int j = 0; j < 4; ++j) {
                int i = tid + (c * 4 + j) * ETHREADS;
                int d4 = i & 15;
                int eg = e0 + (i >> 4); if (eg >= E) eg = E - 1;
                va[j] = ((const float4*)(h + (size_t)ss[j] * 64))[d4];
                vb[j] = ((const float4*)(h + (size_t)dd[j] * 64))[d4];
                ve[j] = ((const float4*)(eh + (size_t)eg * 64))[d4];
            }
#pragma unroll
            for (int j = 0; j < 4; ++j) {
                int i = tid + (c * 4 + j) * ETHREADS;
                int e = i >> 4, d4 = i & 15;
                *(uint2*)(smem + SA_OFF + e * STRIDE128 + d4 * 8) =
                    pack4_bf16(va[j].x * vb[j].x, va[j].y * vb[j].y,
                               va[j].z * vb[j].z, va[j].w * vb[j].w);
                *(uint2*)(smem + SA_OFF + e * STRIDE128 + 128 + d4 * 8) =
                    pack4_bf16(ve[j].x, ve[j].y, ve[j].z, ve[j].w);
            }
        }
        CP_WAIT0();
        __syncthreads();   // [3] A + idx + Wcomb ready

        // ---- stage A: x2 = relu(A @ Wcomb + b2) -> SA in place ----
        {
            float acc[2][2][4][4];
            mma_stage2<8, 4>(sbase + SA_OFF, STRIDE128, sbase + WBUF_OFF, STRIDE128, m0, n0w, lane, acc);
            __syncthreads();   // [4] all A + Wcomb reads done -> safe to overwrite
            cp_w(sbase + WBUF_OFF, IWE2, 34816, tid);   // We2 (overlaps epilogue)
#pragma unroll
            for (int hf = 0; hf < 2; ++hf)
#pragma unroll
                for (int mt = 0; mt < 2; ++mt)
#pragma unroll
                    for (int n = 0; n < 4; ++n) {
                        int col = n0w + n * 8 + q * 2;
                        float b0 = sB2[col], b1 = sB2[col + 1];
                        int rA = m0 + hf * 32 + mt * 16 + g;
                        *(uint32_t*)(smem + SA_OFF + rA * STRIDE128 + col * 2) =
                            pack2_bf16(fmaxf(acc[hf][mt][n][0] + b0, 0.f), fmaxf(acc[hf][mt][n][1] + b1, 0.f));
                        *(uint32_t*)(smem + SA_OFF + (rA + 8) * STRIDE128 + col * 2) =
                            pack2_bf16(fmaxf(acc[hf][mt][n][2] + b0, 0.f), fmaxf(acc[hf][mt][n][3] + b1, 0.f));
                    }
        }
        CP_WAIT0();
        __syncthreads();   // [5] x2 + We2 ready

        // ---- stage B: p = Y1[src] * (x2 @ We2) -> SA in place ----
        {
            float acc[2][2][4][4];
            mma_stage2<8, 4>(sbase + SA_OFF, STRIDE128, sbase + WBUF_OFF, STRIDE128, m0, n0w, lane, acc);
            __syncthreads();   // [6] x2 + We2 reads done -> safe to overwrite
            cp_w(sbase + WBUF_OFF, IWC, 18432, tid);    // Wc (overlaps epilogue)
            if (tid == 0) sTile[0] = atomicAdd(&g_ticket, 1);   // next tile ticket
#pragma unroll
            for (int hf = 0; hf < 2; ++hf)
#pragma unroll
                for (int mt = 0; mt < 2; ++mt)
#pragma unroll
                    for (int n = 0; n < 4; ++n) {
                        int col = n0w + n * 8 + q * 2;
                        int rA = m0 + hf * 32 + mt * 16 + g;
                        uint32_t ya = *(const uint32_t*)(g_Y1 + (size_t)sSrc[rA] * 128 + col);
                        uint32_t yb = *(const uint32_t*)(g_Y1 + (size_t)sSrc[rA + 8] * 128 + col);
                        __nv_bfloat162 hA = *(__nv_bfloat162*)&ya;
                        __nv_bfloat162 hB = *(__nv_bfloat162*)&yb;
                        *(uint32_t*)(smem + SA_OFF + rA * STRIDE128 + col * 2) =
                            pack2_bf16(acc[hf][mt][n][0] * __bfloat162float(hA.x),
                                       acc[hf][mt][n][1] * __bfloat162float(hA.y));
                        *(uint32_t*)(smem + SA_OFF + (rA + 8) * STRIDE128 + col * 2) =
                            pack2_bf16(acc[hf][mt][n][2] * __bfloat162float(hB.x),
                                       acc[hf][mt][n][3] * __bfloat162float(hB.y));
                    }
        }
        CP_WAIT0();
        __syncthreads();   // [7] p + Wc ready

        // ---- stage C (4Mx2N): m = tanh(p @ Wc); reduce-add to out[dst] ----
        {
            int dReg[2], egReg[2], dRegB[2], egRegB[2];
#pragma unroll
            for (int mt = 0; mt < 2; ++mt) {
                int rA = m0c + mt * 16 + g;
                dReg[mt] = sDst[rA];  egReg[mt] = e0 + rA;
                dRegB[mt] = sDst[rA + 8]; egRegB[mt] = e0 + rA + 8;
            }

            float a6[2][4][4];
            mma_stage<8, 4>(sbase + SA_OFF, STRIDE128, sbase + WBUF_OFF, STRIDE64, m0c, n0c, lane, a6);
            __syncthreads();   // [8] stage C MMA done: SA/WBUF/sSrc/sDst free
            cp_w(sbase + WBUF_OFF, IWCB, 34816, tid);   // NEXT tile's Wcomb

#pragma unroll
            for (int mt = 0; mt < 2; ++mt) {
#pragma unroll
                for (int n = 0; n < 4; ++n) {
                    int col = n0c + n * 8 + q * 2;
                    if (egReg[mt] < E) {
                        float* p = out + (size_t)dReg[mt] * 64 + col;
                        asm volatile("red.global.add.v2.f32 [%0], {%1,%2};"
                            :: "l"(p), "f"(fast_tanh(a6[mt][n][0])), "f"(fast_tanh(a6[mt][n][1])) : "memory");
                    }
                    if (egRegB[mt] < E) {
                        float* p = out + (size_t)dRegB[mt] * 64 + col;
                        asm volatile("red.global.add.v2.f32 [%0], {%1,%2};"
                            :: "l"(p), "f"(fast_tanh(a6[mt][n][2])), "f"(fast_tanh(a6[mt][n][3])) : "memory");
                    }
                }
            }
        }
        tile = sTile[0];   // written before [7], visible
    }
    CP_WAIT0();   // drain in-flight weight stream before exit
}

extern "C" void kernel_launch(void* const* d_in, const int* in_sizes, int n_in,
                              void* d_out, int out_size) {
    const float* h   = (const float*)d_in[0];
    const float* eh  = (const float*)d_in[1];
    const float* Wn1 = (const float*)d_in[2];
    const float* bn1 = (const float*)d_in[3];
    const float* Wn2 = (const float*)d_in[4];
    const float* We1 = (const float*)d_in[5];
    const float* be1 = (const float*)d_in[6];
    const float* We2 = (const float*)d_in[7];
    const float* Wc  = (const float*)d_in[8];
    const float* Wue = (const float*)d_in[9];
    const int*   src = (const int*)d_in[10];
    const int*   dst = (const int*)d_in[11];
    float* out = (float*)d_out;

    int E = in_sizes[10];
    int Nn = in_sizes[0] / 64;
    if (Nn > N_MAX) Nn = N_MAX;
    int nTiles = (E + M_TILE - 1) / M_TILE;

    void* ticketAddr = nullptr;
    cudaGetSymbolAddress(&ticketAddr, g_ticket);
    cudaMemsetAsync(ticketAddr, 0, sizeof(int));

    int nNodeBlocks = (Nn + 127) / 128;
    cudaFuncSetAttribute(node_kernel, cudaFuncAttributeMaxDynamicSharedMemorySize, NSMEM_BYTES);
    node_kernel<<<nNodeBlocks + 160, NTHREADS, NSMEM_BYTES>>>(
        h, Wn1, bn1, Wn2, Wue, We1, We2, Wc, out, Nn, nNodeBlocks);

    int nSM = 148;
    cudaDeviceGetAttribute(&nSM, cudaDevAttrMultiProcessorCount, 0);
    int grid = 3 * nSM;
    if (grid > nTiles) grid = nTiles;

    cudaFuncSetAttribute(edge_kernel, cudaFuncAttributeMaxDynamicSharedMemorySize, ESMEM_BYTES);
    edge_kernel<<<grid, ETHREADS, ESMEM_BYTES>>>(h, eh, be1, src, dst, out, E, nTiles);
}

// round 16
// speedup vs baseline: 1.1585x; 1.1585x over previous
#include <cuda_runtime.h>
#include <cuda_bf16.h>
#include <math.h>
#include <stdint.h>

#define ETHREADS 256
#define NTHREADS 256
#define M_TILE 128
#define N_MAX 50000

#define STRIDE128 272
#define STRIDE64  144

// ---- padded bf16 weight images ----
#define IWCB 0        // Wcomb [128x128] s272 : 34816
#define IWE2 34816    // We2   [128x128] s272 : 34816
#define IWC  69632    // Wc    [128x64]  s144 : 18432
#define IMG_TOTAL 88064
__device__ __align__(16) unsigned char g_wimg[IMG_TOTAL];

// per-node m1 table: Y1 = relu(h@Wn1+b1)@Wn2, bf16 [N_MAX x 128]
__device__ __align__(16) __nv_bfloat16 g_Y1[(size_t)N_MAX * 128];

// dynamic tile ticket (reset by cudaMemsetAsync each launch)
__device__ int g_ticket;

// ---- edge kernel smem (bytes): two weight buffers + in-place SA ----
#define W0_OFF   0          // 34816 weight buffer 0
#define W1_OFF   34816      // 34816 weight buffer 1
#define SA_OFF   69632      // 34816 A = [t|eh] -> x2 -> p (in place)
#define SB2_OFF  104448     // 512
#define SSRC_OFF 104960     // 512
#define SDST_OFF 105472     // 512
#define STILE_OFF 105984    // 16
#define ESMEM_BYTES 106000  // x2 CTAs = 212000 < 227KB

// ---- node kernel smem ----
#define NW1_OFF 0
#define NW2_OFF (NW1_OFF + 64*STRIDE128)
#define NH_OFF  (NW2_OFF + 128*STRIDE128)
#define NX_OFF  (NH_OFF + 128*STRIDE64)
#define NB_OFF  (NX_OFF + 128*STRIDE128)
#define NSMEM_BYTES (NB_OFF + 512)

__device__ __forceinline__ uint32_t smem_u32(const void* p) {
    uint32_t a;
    asm("{ .reg .u64 t; cvta.to.shared.u64 t, %1; cvt.u32.u64 %0, t; }" : "=r"(a) : "l"(p));
    return a;
}
__device__ __forceinline__ uint32_t pack2_bf16(float a, float b) {
    __nv_bfloat162 p = __float22bfloat162_rn(make_float2(a, b));
    return *(unsigned int*)&p;
}
__device__ __forceinline__ uint2 pack4_bf16(float a, float b, float c, float d) {
    uint2 r; r.x = pack2_bf16(a, b); r.y = pack2_bf16(c, d); return r;
}
__device__ __forceinline__ float fast_tanh(float x) {
    float y;
    asm("tanh.approx.f32 %0, %1;" : "=f"(y) : "f"(x));
    return y;
}
__device__ __forceinline__ void ldsm_x4(uint32_t addr, uint32_t r[4]) {
    asm volatile("ldmatrix.sync.aligned.m8n8.x4.shared.b16 {%0,%1,%2,%3}, [%4];"
        : "=r"(r[0]), "=r"(r[1]), "=r"(r[2]), "=r"(r[3]) : "r"(addr));
}
__device__ __forceinline__ void ldsm_x4t(uint32_t addr, uint32_t r[4]) {
    asm volatile("ldmatrix.sync.aligned.m8n8.x4.trans.shared.b16 {%0,%1,%2,%3}, [%4];"
        : "=r"(r[0]), "=r"(r[1]), "=r"(r[2]), "=r"(r[3]) : "r"(addr));
}
__device__ __forceinline__ void mma16816(float d[4], const uint32_t a[4], const uint32_t b[2]) {
    asm volatile("mma.sync.aligned.m16n8k16.row.col.f32.bf16.bf16.f32 "
        "{%0,%1,%2,%3},{%4,%5,%6,%7},{%8,%9},{%0,%1,%2,%3};"
        : "+f"(d[0]), "+f"(d[1]), "+f"(d[2]), "+f"(d[3])
        : "r"(a[0]), "r"(a[1]), "r"(a[2]), "r"(a[3]), "r"(b[0]), "r"(b[1]));
}

// cp.async weight stream (one commit group per call)
__device__ __forceinline__ void cp_w(uint32_t sdst, int img_off, int bytes, int tid) {
    const unsigned char* gsrc = g_wimg + img_off;
    for (int i = tid * 16; i < bytes; i += ETHREADS * 16)
        asm volatile("cp.async.cg.shared.global [%0], [%1], 16;"
                     :: "r"(sdst + i), "l"(gsrc + i));
    asm volatile("cp.async.commit_group;");
}
#define CP_WAIT1() asm volatile("cp.async.wait_group 1;" ::: "memory")
#define CP_WAIT0() asm volatile("cp.async.wait_group 0;" ::: "memory")

// warp covers 64 rows (2 halves x 2 m16 tiles), B frags reused across halves
template<int KT, int NTH>
__device__ __forceinline__ void mma_stage2(uint32_t aAddr, int aStride,
                                           uint32_t wAddr, int wStride,
                                           int m0, int n0, int lane,
                                           float acc[2][2][NTH][4]) {
#pragma unroll
    for (int hf = 0; hf < 2; ++hf)
#pragma unroll
        for (int mt = 0; mt < 2; ++mt)
#pragma unroll
            for (int n = 0; n < NTH; ++n)
#pragma unroll
                for (int e = 0; e < 4; ++e) acc[hf][mt][n][e] = 0.f;
    const int krow = lane & 15;
    const int xoff = (lane >> 4) << 3;
#pragma unroll
    for (int k = 0; k < KT; ++k) {
        uint32_t b[NTH / 2][4];
#pragma unroll
        for (int np = 0; np < NTH / 2; ++np)
            ldsm_x4t(wAddr + (uint32_t)(k * 16 + krow) * wStride + (uint32_t)(n0 + np * 16 + xoff) * 2, b[np]);
#pragma unroll
        for (int hf = 0; hf < 2; ++hf) {
            uint32_t a[2][4];
#pragma unroll
            for (int mt = 0; mt < 2; ++mt)
                ldsm_x4(aAddr + (uint32_t)(m0 + hf * 32 + mt * 16 + krow) * aStride + (uint32_t)(k * 16 + xoff) * 2, a[mt]);
#pragma unroll
            for (int np = 0; np < NTH / 2; ++np) {
                mma16816(acc[hf][0][np * 2 + 0], a[0], b[np] + 0);
                mma16816(acc[hf][1][np * 2 + 0], a[1], b[np] + 0);
                mma16816(acc[hf][0][np * 2 + 1], a[0], b[np] + 2);
                mma16816(acc[hf][1][np * 2 + 1], a[1], b[np] + 2);
            }
        }
    }
}

// single-strip version: warp covers 32 rows (2 m16 tiles) x NTH*8 cols
template<int KT, int NTH>
__device__ __forceinline__ void mma_stage(uint32_t aAddr, int aStride,
                                          uint32_t wAddr, int wStride,
                                          int m0, int n0, int lane,
                                          float acc[2][NTH][4]) {
#pragma unroll
    for (int mt = 0; mt < 2; ++mt)
#pragma unroll
        for (int n = 0; n < NTH; ++n)
#pragma unroll
            for (int e = 0; e < 4; ++e) acc[mt][n][e] = 0.f;
    const int krow = lane & 15;
    const int xoff = (lane >> 4) << 3;
#pragma unroll
    for (int k = 0; k < KT; ++k) {
        uint32_t a[2][4];
#pragma unroll
        for (int mt = 0; mt < 2; ++mt)
            ldsm_x4(aAddr + (uint32_t)(m0 + mt * 16 + krow) * aStride + (uint32_t)(k * 16 + xoff) * 2, a[mt]);
#pragma unroll
        for (int np = 0; np < NTH / 2; ++np) {
            uint32_t b[4];
            ldsm_x4t(wAddr + (uint32_t)(k * 16 + krow) * wStride + (uint32_t)(n0 + np * 16 + xoff) * 2, b);
            mma16816(acc[0][np * 2 + 0], a[0], b + 0);
            mma16816(acc[1][np * 2 + 0], a[1], b + 0);
            mma16816(acc[0][np * 2 + 1], a[0], b + 2);
            mma16816(acc[1][np * 2 + 1], a[1], b + 2);
        }
    }
}

__device__ __forceinline__ void load_weight_smem(char* smemc, int off, const float* __restrict__ W,
                                                 int K, int N, int stride, int tid, int nthr) {
    int n4 = (K * N) >> 2;
    for (int i = tid; i < n4; i += nthr) {
        int idx = i << 2;
        int r = idx / N, c = idx % N;
        float4 v = *(const float4*)(W + idx);
        *(uint2*)(smemc + off + r * stride + c * 2) = pack4_bf16(v.x, v.y, v.z, v.w);
    }
}

// =============== node kernel: Y1 table + residual init + weight conversion ===============
__global__ __launch_bounds__(NTHREADS)
void node_kernel(const float* __restrict__ h,
                 const float* __restrict__ Wn1, const float* __restrict__ bn1,
                 const float* __restrict__ Wn2,
                 const float* __restrict__ Wue, const float* __restrict__ We1,
                 const float* __restrict__ We2, const float* __restrict__ Wc,
                 float* __restrict__ out, int Nn, int nNodeBlocks)
{
    if (blockIdx.x >= nNodeBlocks) {
        int i = (blockIdx.x - nNodeBlocks) * NTHREADS + threadIdx.x;
        if (i < 16384) {                // Wcomb = [[0.2*Wue@We1],[0.8*We1]]
            int r = i >> 7, c = i & 127;
            float v;
            if (r < 64) {
                float s = 0.f;
#pragma unroll 8
                for (int k = 0; k < 64; ++k) s += Wue[r * 64 + k] * We1[k * 128 + c];
                v = 0.2f * s;
            } else {
                v = 0.8f * We1[(r - 64) * 128 + c];
            }
            *(__nv_bfloat16*)(g_wimg + IWCB + r * STRIDE128 + c * 2) = __float2bfloat16(v);
        } else if (i < 32768) {         // We2
            int j = i - 16384, r = j >> 7, c = j & 127;
            *(__nv_bfloat16*)(g_wimg + IWE2 + r * STRIDE128 + c * 2) = __float2bfloat16(We2[j]);
        } else if (i < 40960) {         // Wc
            int j = i - 32768, r = j >> 6, c = j & 63;
            *(__nv_bfloat16*)(g_wimg + IWC + r * STRIDE64 + c * 2) = __float2bfloat16(Wc[j]);
        }
        return;
    }

    extern __shared__ char smem[];
    const uint32_t sbase = smem_u32(smem);
    const int tid = threadIdx.x;
    const int warp = tid >> 5;
    const int lane = tid & 31;
    const int mi = warp >> 1, nj = warp & 1;
    const int m0 = mi * 32, n0 = nj * 64;
    const int g = lane >> 2, q = lane & 3;
    const int r0 = blockIdx.x * 128;

    float* sB = (float*)(smem + NB_OFF);
    load_weight_smem(smem, NW1_OFF, Wn1, 64, 128, STRIDE128, tid, NTHREADS);
    load_weight_smem(smem, NW2_OFF, Wn2, 128, 128, STRIDE128, tid, NTHREADS);
    if (tid < 128) sB[tid] = bn1[tid];

    for (int i = tid; i < 128 * 16; i += NTHREADS) {
        int r = i >> 4, d4 = i & 15;
        int nr = r0 + r;
        bool valid = (nr < Nn);
        if (!valid) nr = Nn - 1;
        float4 v = ((const float4*)(h + (size_t)nr * 64))[d4];
        if (valid) ((float4*)(out + (size_t)nr * 64))[d4] = v;
        *(uint2*)(smem + NH_OFF + r * STRIDE64 + d4 * 8) = pack4_bf16(v.x, v.y, v.z, v.w);
    }
    __syncthreads();

    float acc[2][8][4];
    mma_stage<4, 8>(sbase + NH_OFF, STRIDE64, sbase + NW1_OFF, STRIDE128, m0, n0, lane, acc);
#pragma unroll
    for (int mt = 0; mt < 2; ++mt)
#pragma unroll
        for (int n = 0; n < 8; ++n) {
            int col = n0 + n * 8 + q * 2;
            float b0 = sB[col], b1 = sB[col + 1];
            int rA = m0 + mt * 16 + g;
            *(uint32_t*)(smem + NX_OFF + rA * STRIDE128 + col * 2) =
                pack2_bf16(fmaxf(acc[mt][n][0] + b0, 0.f), fmaxf(acc[mt][n][1] + b1, 0.f));
            *(uint32_t*)(smem + NX_OFF + (rA + 8) * STRIDE128 + col * 2) =
                pack2_bf16(fmaxf(acc[mt][n][2] + b0, 0.f), fmaxf(acc[mt][n][3] + b1, 0.f));
        }
    __syncthreads();

    mma_stage<8, 8>(sbase + NX_OFF, STRIDE128, sbase + NW2_OFF, STRIDE128, m0, n0, lane, acc);
#pragma unroll
    for (int mt = 0; mt < 2; ++mt)
#pragma unroll
        for (int n = 0; n < 8; ++n) {
            int col = n0 + n * 8 + q * 2;
            int rA = m0 + mt * 16 + g;
            int nrA = r0 + rA, nrB = r0 + rA + 8;
            if (nrA < Nn)
                *(uint32_t*)(g_Y1 + (size_t)nrA * 128 + col) = pack2_bf16(acc[mt][n][0], acc[mt][n][1]);
            if (nrB < Nn)
                *(uint32_t*)(g_Y1 + (size_t)nrB * 128 + col) = pack2_bf16(acc[mt][n][2], acc[mt][n][3]);
        }
}

// =============== edge kernel: 2 CTAs/SM, double-buffered weights, in-place acts ===============
__global__ __launch_bounds__(ETHREADS, 2)
void edge_kernel(const float* __restrict__ h, const float* __restrict__ eh,
                 const float* __restrict__ be1,
                 const int* __restrict__ src, const int* __restrict__ dst,
                 float* __restrict__ out, int E, int nTiles)
{
    extern __shared__ char smem[];
    const uint32_t sbase = smem_u32(smem);
    const int tid = threadIdx.x;
    const int warp = tid >> 5;
    const int lane = tid & 31;

    // stages A/B: 2 M-strips (64 rows) x 4 N-quarters
    const int mi = warp >> 2;
    const int nj = warp & 3;
    const int m0 = mi * 64;
    const int n0w = nj * 32;   // N=128 (NTH=4)
    // stage C remap: 4 M-strips (32 rows) x 2 N-halves
    const int m0c = (warp & 3) * 32;
    const int n0c = (warp >> 2) * 32;
    const int g = lane >> 2, q = lane & 3;

    float* sB2 = (float*)(smem + SB2_OFF);
    int* sSrc = (int*)(smem + SSRC_OFF);
    int* sDst = (int*)(smem + SDST_OFF);
    int* sTile = (int*)(smem + STILE_OFF);

    if (tid < 128) sB2[tid] = be1[tid];

    // prologue: ticket + Wcomb->W0, We2->W1 (2 groups in flight)
    if (tid == 0) sTile[0] = atomicAdd(&g_ticket, 1);
    cp_w(sbase + W0_OFF, IWCB, 34816, tid);
    cp_w(sbase + W1_OFF, IWE2, 34816, tid);
    __syncthreads();
    int tile = sTile[0];
    int par = 0;

    while (tile < nTiles) {
        const int e0 = tile * M_TILE;
        const uint32_t bufA = sbase + (par ? W1_OFF : W0_OFF);  // Wcomb, then Wc
        const uint32_t bufB = sbase + (par ? W0_OFF : W1_OFF);  // We2, then next Wcomb

        // idx -> smem + gather with direct broadcast LDG
        if (tid < M_TILE) {
            int eg = e0 + tid; if (eg >= E) eg = E - 1;
            sSrc[tid] = src[eg];
            sDst[tid] = dst[eg];
        }
#pragma unroll
        for (int c = 0; c < 2; ++c) {
            int ss[4], dd[4];
            float4 va[4], vb[4], ve[4];
#pragma unroll
            for (int j = 0; j < 4; ++j) {
                int i = tid + (c * 4 + j) * ETHREADS;
                int e = i >> 4;
                int eg = e0 + e; if (eg >= E) eg = E - 1;
                ss[j] = src[eg]; dd[j] = dst[eg];
            }
#pragma unroll
            for (int j = 0; j < 4; ++j) {
                int i = tid + (c * 4 + j) * ETHREADS;
                int d4 = i & 15;
                int eg = e0 + (i >> 4); if (eg >= E) eg = E - 1;
                va[j] = ((const float4*)(h + (size_t)ss[j] * 64))[d4];
                vb[j] = ((const float4*)(h + (size_t)dd[j] * 64))[d4];
                ve[j] = ((const float4*)(eh + (size_t)eg * 64))[d4];
            }
#pragma unroll
            for (int j = 0; j < 4; ++j) {
                int i = tid + (c * 4 + j) * ETHREADS;
                int e = i >> 4, d4 = i & 15;
                *(uint2*)(smem + SA_OFF + e * STRIDE128 + d4 * 8) =
                    pack4_bf16(va[j].x * vb[j].x, va[j].y * vb[j].y,
                               va[j].z * vb[j].z, va[j].w * vb[j].w);
                *(uint2*)(smem + SA_OFF + e * STRIDE128 + 128 + d4 * 8) =
                    pack4_bf16(ve[j].x, ve[j].y, ve[j].z, ve[j].w);
            }
        }
        CP_WAIT1();        // Wcomb (bufA) done; We2 may still be in flight
        __syncthreads();   // [3] A + idx + Wcomb ready

        // ---- stage A: x2 = relu(A @ Wcomb + b2) -> SA in place ----
        {
            float acc[2][2][4][4];
            mma_stage2<8, 4>(sbase + SA_OFF, STRIDE128, bufA, STRIDE128, m0, n0w, lane, acc);
            __syncthreads();   // [4] all A + Wcomb reads done
            cp_w(bufA, IWC, 18432, tid);        // Wc -> bufA (hidden under epilogue + stage B)
#pragma unroll
            for (int hf = 0; hf < 2; ++hf)
#pragma unroll
                for (int mt = 0; mt < 2; ++mt)
#pragma unroll
                    for (int n = 0; n < 4; ++n) {
                        int col = n0w + n * 8 + q * 2;
                        float b0 = sB2[col], b1 = sB2[col + 1];
                        int rA = m0 + hf * 32 + mt * 16 + g;
                        *(uint32_t*)(smem + SA_OFF + rA * STRIDE128 + col * 2) =
                            pack2_bf16(fmaxf(acc[hf][mt][n][0] + b0, 0.f), fmaxf(acc[hf][mt][n][1] + b1, 0.f));
                        *(uint32_t*)(smem + SA_OFF + (rA + 8) * STRIDE128 + col * 2) =
                            pack2_bf16(fmaxf(acc[hf][mt][n][2] + b0, 0.f), fmaxf(acc[hf][mt][n][3] + b1, 0.f));
                    }
        }
        CP_WAIT1();        // We2 (bufB) done; Wc may still be in flight
        __syncthreads();   // [5] x2 + We2 ready

        // ---- stage B: p = Y1[src] * (x2 @ We2) -> SA in place ----
        {
            float acc[2][2][4][4];
            mma_stage2<8, 4>(sbase + SA_OFF, STRIDE128, bufB, STRIDE128, m0, n0w, lane, acc);
            __syncthreads();   // [6] x2 + We2 reads done
            cp_w(bufB, IWCB, 34816, tid);       // NEXT tile's Wcomb -> bufB
            if (tid == 0) sTile[0] = atomicAdd(&g_ticket, 1);   // next tile ticket
#pragma unroll
            for (int hf = 0; hf < 2; ++hf)
#pragma unroll
                for (int mt = 0; mt < 2; ++mt)
#pragma unroll
                    for (int n = 0; n < 4; ++n) {
                        int col = n0w + n * 8 + q * 2;
                        int rA = m0 + hf * 32 + mt * 16 + g;
                        uint32_t ya = *(const uint32_t*)(g_Y1 + (size_t)sSrc[rA] * 128 + col);
                        uint32_t yb = *(const uint32_t*)(g_Y1 + (size_t)sSrc[rA + 8] * 128 + col);
                        __nv_bfloat162 hA = *(__nv_bfloat162*)&ya;
                        __nv_bfloat162 hB = *(__nv_bfloat162*)&yb;
                        *(uint32_t*)(smem + SA_OFF + rA * STRIDE128 + col * 2) =
                            pack2_bf16(acc[hf][mt][n][0] * __bfloat162float(hA.x),
                                       acc[hf][mt][n][1] * __bfloat162float(hA.y));
                        *(uint32_t*)(smem + SA_OFF + (rA + 8) * STRIDE128 + col * 2) =
                            pack2_bf16(acc[hf][mt][n][2] * __bfloat162float(hB.x),
                                       acc[hf][mt][n][3] * __bfloat162float(hB.y));
                    }
        }
        CP_WAIT1();        // Wc (bufA) done; next Wcomb may still be in flight
        __syncthreads();   // [7] p + Wc ready

        // ---- stage C (4Mx2N): m = tanh(p @ Wc); reduce-add to out[dst] ----
        {
            int dReg[2], egReg[2], dRegB[2], egRegB[2];
#pragma unroll
            for (int mt = 0; mt < 2; ++mt) {
                int rA = m0c + mt * 16 + g;
                dReg[mt] = sDst[rA];  egReg[mt] = e0 + rA;
                dRegB[mt] = sDst[rA + 8]; egRegB[mt] = e0 + rA + 8;
            }

            float a6[2][4][4];
            mma_stage<8, 4>(sbase + SA_OFF, STRIDE128, bufA, STRIDE64, m0c, n0c, lane, a6);
            __syncthreads();   // [8] stage C MMA done: SA/bufA/sSrc/sDst free
            cp_w(bufA, IWE2, 34816, tid);       // NEXT tile's We2 -> bufA (hidden under epi + gather)

#pragma unroll
            for (int mt = 0; mt < 2; ++mt) {
#pragma unroll
                for (int n = 0; n < 4; ++n) {
                    int col = n0c + n * 8 + q * 2;
                    if (egReg[mt] < E) {
                        float* p = out + (size_t)dReg[mt] * 64 + col;
                        asm volatile("red.global.add.v2.f32 [%0], {%1,%2};"
                            :: "l"(p), "f"(fast_tanh(a6[mt][n][0])), "f"(fast_tanh(a6[mt][n][1])) : "memory");
                    }
                    if (egRegB[mt] < E) {
                        float* p = out + (size_t)dRegB[mt] * 64 + col;
                        asm volatile("red.global.add.v2.f32 [%0], {%1,%2};"
                            :: "l"(p), "f"(fast_tanh(a6[mt][n][2])), "f"(fast_tanh(a6[mt][n][3])) : "memory");
                    }
                }
            }
        }
        par ^= 1;          // next tile: Wcomb in bufB, We2 in bufA
        tile = sTile[0];   // written before [7], visible
    }
    CP_WAIT0();   // drain in-flight weight streams before exit
}

extern "C" void kernel_launch(void* const* d_in, const int* in_sizes, int n_in,
                              void* d_out, int out_size) {
    const float* h   = (const float*)d_in[0];
    const float* eh  = (const float*)d_in[1];
    const float* Wn1 = (const float*)d_in[2];
    const float* bn1 = (const float*)d_in[3];
    const float* Wn2 = (const float*)d_in[4];
    const float* We1 = (const float*)d_in[5];
    const float* be1 = (const float*)d_in[6];
    const float* We2 = (const float*)d_in[7];
    const float* Wc  = (const float*)d_in[8];
    const float* Wue = (const float*)d_in[9];
    const int*   src = (const int*)d_in[10];
    const int*   dst = (const int*)d_in[11];
    float* out = (float*)d_out;

    int E = in_sizes[10];
    int Nn = in_sizes[0] / 64;
    if (Nn > N_MAX) Nn = N_MAX;
    int nTiles = (E + M_TILE - 1) / M_TILE;

    void* ticketAddr = nullptr;
    cudaGetSymbolAddress(&ticketAddr, g_ticket);
    cudaMemsetAsync(ticketAddr, 0, sizeof(int));

    int nNodeBlocks = (Nn + 127) / 128;
    cudaFuncSetAttribute(node_kernel, cudaFuncAttributeMaxDynamicSharedMemorySize, NSMEM_BYTES);
    node_kernel<<<nNodeBlocks + 160, NTHREADS, NSMEM_BYTES>>>(
        h, Wn1, bn1, Wn2, Wue, We1, We2, Wc, out, Nn, nNodeBlocks);

    int nSM = 148;
    cudaDeviceGetAttribute(&nSM, cudaDevAttrMultiProcessorCount, 0);
    int grid = 2 * nSM;
    if (grid > nTiles) grid = nTiles;

    cudaFuncSetAttribute(edge_kernel, cudaFuncAttributeMaxDynamicSharedMemorySize, ESMEM_BYTES);
    edge_kernel<<<grid, ETHREADS, ESMEM_BYTES>>>(h, eh, be1, src, dst, out, E, nTiles);
}

// round 17
// speedup vs baseline: 1.2630x; 1.0902x over previous
#include <cuda_runtime.h>
#include <cuda_bf16.h>
#include <math.h>
#include <stdint.h>

#define ETHREADS 256
#define NTHREADS 256
#define M_TILE 128
#define N_MAX 50000

#define STRIDE128 272
#define STRIDE64  144

// ---- padded bf16 weight images ----
#define IWCB 0        // Wcomb [128x128] s272 : 34816
#define IWE2 34816    // We2   [128x128] s272 : 34816
#define IWC  69632    // Wc    [128x64]  s144 : 18432
#define IMG_TOTAL 88064
__device__ __align__(16) unsigned char g_wimg[IMG_TOTAL];

// per-node m1 table: Y1 = relu(h@Wn1+b1)@Wn2, bf16 [N_MAX x 128]
__device__ __align__(16) __nv_bfloat16 g_Y1[(size_t)N_MAX * 128];

// dynamic tile ticket (reset by node_kernel each launch)
__device__ int g_ticket;

// ---- edge kernel smem (bytes) ----
#define WBUF_OFF 0          // 34816 streamed weight
#define SA_OFF   34816      // 34816 A = [t | eh] -> p
#define SX_OFF   69632      // 34816 x2
#define SB2_OFF  104448     // 512
#define SSRC_OFF 104960     // 512
#define SDST_OFF 105472     // 512
#define STILE_OFF 105984    // 16
#define ESMEM_BYTES 106000

// ---- node kernel smem ----
#define NW1_OFF 0
#define NW2_OFF (NW1_OFF + 64*STRIDE128)
#define NH_OFF  (NW2_OFF + 128*STRIDE128)
#define NX_OFF  (NH_OFF + 128*STRIDE64)
#define NB_OFF  (NX_OFF + 128*STRIDE128)
#define NSMEM_BYTES (NB_OFF + 512)

__device__ __forceinline__ uint32_t smem_u32(const void* p) {
    uint32_t a;
    asm("{ .reg .u64 t; cvta.to.shared.u64 t, %1; cvt.u32.u64 %0, t; }" : "=r"(a) : "l"(p));
    return a;
}
__device__ __forceinline__ uint32_t pack2_bf16(float a, float b) {
    __nv_bfloat162 p = __float22bfloat162_rn(make_float2(a, b));
    return *(unsigned int*)&p;
}
__device__ __forceinline__ uint2 pack4_bf16(float a, float b, float c, float d) {
    uint2 r; r.x = pack2_bf16(a, b); r.y = pack2_bf16(c, d); return r;
}
__device__ __forceinline__ float fast_tanh(float x) {
    float y;
    asm("tanh.approx.f32 %0, %1;" : "=f"(y) : "f"(x));
    return y;
}
__device__ __forceinline__ void ldsm_x4(uint32_t addr, uint32_t r[4]) {
    asm volatile("ldmatrix.sync.aligned.m8n8.x4.shared.b16 {%0,%1,%2,%3}, [%4];"
        : "=r"(r[0]), "=r"(r[1]), "=r"(r[2]), "=r"(r[3]) : "r"(addr));
}
__device__ __forceinline__ void ldsm_x4t(uint32_t addr, uint32_t r[4]) {
    asm volatile("ldmatrix.sync.aligned.m8n8.x4.trans.shared.b16 {%0,%1,%2,%3}, [%4];"
        : "=r"(r[0]), "=r"(r[1]), "=r"(r[2]), "=r"(r[3]) : "r"(addr));
}
__device__ __forceinline__ void mma16816(float d[4], const uint32_t a[4], const uint32_t b[2]) {
    asm volatile("mma.sync.aligned.m16n8k16.row.col.f32.bf16.bf16.f32 "
        "{%0,%1,%2,%3},{%4,%5,%6,%7},{%8,%9},{%0,%1,%2,%3};"
        : "+f"(d[0]), "+f"(d[1]), "+f"(d[2]), "+f"(d[3])
        : "r"(a[0]), "r"(a[1]), "r"(a[2]), "r"(a[3]), "r"(b[0]), "r"(b[1]));
}

// cp.async weight stream
__device__ __forceinline__ void cp_w(uint32_t sdst, int img_off, int bytes, int tid) {
    const unsigned char* gsrc = g_wimg + img_off;
    for (int i = tid * 16; i < bytes; i += ETHREADS * 16)
        asm volatile("cp.async.cg.shared.global [%0], [%1], 16;"
                     :: "r"(sdst + i), "l"(gsrc + i));
    asm volatile("cp.async.commit_group;");
}
#define CP_WAIT0() asm volatile("cp.async.wait_group 0;" ::: "memory")

// warp covers 64 rows (2 halves x 2 m16 tiles), B frags reused across halves
template<int KT, int NTH>
__device__ __forceinline__ void mma_stage2(uint32_t aAddr, int aStride,
                                           uint32_t wAddr, int wStride,
                                           int m0, int n0, int lane,
                                           float acc[2][2][NTH][4]) {
#pragma unroll
    for (int hf = 0; hf < 2; ++hf)
#pragma unroll
        for (int mt = 0; mt < 2; ++mt)
#pragma unroll
            for (int n = 0; n < NTH; ++n)
#pragma unroll
                for (int e = 0; e < 4; ++e) acc[hf][mt][n][e] = 0.f;
    const int krow = lane & 15;
    const int xoff = (lane >> 4) << 3;
#pragma unroll
    for (int k = 0; k < KT; ++k) {
        uint32_t b[NTH / 2][4];
#pragma unroll
        for (int np = 0; np < NTH / 2; ++np)
            ldsm_x4t(wAddr + (uint32_t)(k * 16 + krow) * wStride + (uint32_t)(n0 + np * 16 + xoff) * 2, b[np]);
#pragma unroll
        for (int hf = 0; hf < 2; ++hf) {
            uint32_t a[2][4];
#pragma unroll
            for (int mt = 0; mt < 2; ++mt)
                ldsm_x4(aAddr + (uint32_t)(m0 + hf * 32 + mt * 16 + krow) * aStride + (uint32_t)(k * 16 + xoff) * 2, a[mt]);
#pragma unroll
            for (int np = 0; np < NTH / 2; ++np) {
                mma16816(acc[hf][0][np * 2 + 0], a[0], b[np] + 0);
                mma16816(acc[hf][1][np * 2 + 0], a[1], b[np] + 0);
                mma16816(acc[hf][0][np * 2 + 1], a[0], b[np] + 2);
                mma16816(acc[hf][1][np * 2 + 1], a[1], b[np] + 2);
            }
        }
    }
}

// single-strip version: warp covers 32 rows (2 m16 tiles) x NTH*8 cols
template<int KT, int NTH>
__device__ __forceinline__ void mma_stage(uint32_t aAddr, int aStride,
                                          uint32_t wAddr, int wStride,
                                          int m0, int n0, int lane,
                                          float acc[2][NTH][4]) {
#pragma unroll
    for (int mt = 0; mt < 2; ++mt)
#pragma unroll
        for (int n = 0; n < NTH; ++n)
#pragma unroll
            for (int e = 0; e < 4; ++e) acc[mt][n][e] = 0.f;
    const int krow = lane & 15;
    const int xoff = (lane >> 4) << 3;
#pragma unroll
    for (int k = 0; k < KT; ++k) {
        uint32_t a[2][4];
#pragma unroll
        for (int mt = 0; mt < 2; ++mt)
            ldsm_x4(aAddr + (uint32_t)(m0 + mt * 16 + krow) * aStride + (uint32_t)(k * 16 + xoff) * 2, a[mt]);
#pragma unroll
        for (int np = 0; np < NTH / 2; ++np) {
            uint32_t b[4];
            ldsm_x4t(wAddr + (uint32_t)(k * 16 + krow) * wStride + (uint32_t)(n0 + np * 16 + xoff) * 2, b);
            mma16816(acc[0][np * 2 + 0], a[0], b + 0);
            mma16816(acc[1][np * 2 + 0], a[1], b + 0);
            mma16816(acc[0][np * 2 + 1], a[0], b + 2);
            mma16816(acc[1][np * 2 + 1], a[1], b + 2);
        }
    }
}

__device__ __forceinline__ void load_weight_smem(char* smemc, int off, const float* __restrict__ W,
                                                 int K, int N, int stride, int tid, int nthr) {
    int n4 = (K * N) >> 2;
    for (int i = tid; i < n4; i += nthr) {
        int idx = i << 2;
        int r = idx / N, c = idx % N;
        float4 v = *(const float4*)(W + idx);
        *(uint2*)(smemc + off + r * stride + c * 2) = pack4_bf16(v.x, v.y, v.z, v.w);
    }
}

// =============== node kernel: Y1 table + residual init + weight conversion + ticket reset ===============
__global__ __launch_bounds__(NTHREADS)
void node_kernel(const float* __restrict__ h,
                 const float* __restrict__ Wn1, const float* __restrict__ bn1,
                 const float* __restrict__ Wn2,
                 const float* __restrict__ Wue, const float* __restrict__ We1,
                 const float* __restrict__ We2, const float* __restrict__ Wc,
                 float* __restrict__ out, int Nn, int nNodeBlocks)
{
    if (blockIdx.x >= nNodeBlocks) {
        int i = (blockIdx.x - nNodeBlocks) * NTHREADS + threadIdx.x;
        if (blockIdx.x == (unsigned)nNodeBlocks && threadIdx.x == 0)
            g_ticket = 0;               // ticket reset folded in (stream-ordered before edge kernel)
        if (i < 16384) {                // Wcomb = [[0.2*Wue@We1],[0.8*We1]]
            int r = i >> 7, c = i & 127;
            float v;
            if (r < 64) {
                float s = 0.f;
#pragma unroll 8
                for (int k = 0; k < 64; ++k) s += Wue[r * 64 + k] * We1[k * 128 + c];
                v = 0.2f * s;
            } else {
                v = 0.8f * We1[(r - 64) * 128 + c];
            }
            *(__nv_bfloat16*)(g_wimg + IWCB + r * STRIDE128 + c * 2) = __float2bfloat16(v);
        } else if (i < 32768) {         // We2
            int j = i - 16384, r = j >> 7, c = j & 127;
            *(__nv_bfloat16*)(g_wimg + IWE2 + r * STRIDE128 + c * 2) = __float2bfloat16(We2[j]);
        } else if (i < 40960) {         // Wc
            int j = i - 32768, r = j >> 6, c = j & 63;
            *(__nv_bfloat16*)(g_wimg + IWC + r * STRIDE64 + c * 2) = __float2bfloat16(Wc[j]);
        }
        return;
    }

    extern __shared__ char smem[];
    const uint32_t sbase = smem_u32(smem);
    const int tid = threadIdx.x;
    const int warp = tid >> 5;
    const int lane = tid & 31;
    const int mi = warp >> 1, nj = warp & 1;
    const int m0 = mi * 32, n0 = nj * 64;
    const int g = lane >> 2, q = lane & 3;
    const int r0 = blockIdx.x * 128;

    float* sB = (float*)(smem + NB_OFF);
    load_weight_smem(smem, NW1_OFF, Wn1, 64, 128, STRIDE128, tid, NTHREADS);
    load_weight_smem(smem, NW2_OFF, Wn2, 128, 128, STRIDE128, tid, NTHREADS);
    if (tid < 128) sB[tid] = bn1[tid];

    for (int i = tid; i < 128 * 16; i += NTHREADS) {
        int r = i >> 4, d4 = i & 15;
        int nr = r0 + r;
        bool valid = (nr < Nn);
        if (!valid) nr = Nn - 1;
        float4 v = ((const float4*)(h + (size_t)nr * 64))[d4];
        if (valid) ((float4*)(out + (size_t)nr * 64))[d4] = v;
        *(uint2*)(smem + NH_OFF + r * STRIDE64 + d4 * 8) = pack4_bf16(v.x, v.y, v.z, v.w);
    }
    __syncthreads();

    float acc[2][8][4];
    mma_stage<4, 8>(sbase + NH_OFF, STRIDE64, sbase + NW1_OFF, STRIDE128, m0, n0, lane, acc);
#pragma unroll
    for (int mt = 0; mt < 2; ++mt)
#pragma unroll
        for (int n = 0; n < 8; ++n) {
            int col = n0 + n * 8 + q * 2;
            float b0 = sB[col], b1 = sB[col + 1];
            int rA = m0 + mt * 16 + g;
            *(uint32_t*)(smem + NX_OFF + rA * STRIDE128 + col * 2) =
                pack2_bf16(fmaxf(acc[mt][n][0] + b0, 0.f), fmaxf(acc[mt][n][1] + b1, 0.f));
            *(uint32_t*)(smem + NX_OFF + (rA + 8) * STRIDE128 + col * 2) =
                pack2_bf16(fmaxf(acc[mt][n][2] + b0, 0.f), fmaxf(acc[mt][n][3] + b1, 0.f));
        }
    __syncthreads();

    mma_stage<8, 8>(sbase + NX_OFF, STRIDE128, sbase + NW2_OFF, STRIDE128, m0, n0, lane, acc);
#pragma unroll
    for (int mt = 0; mt < 2; ++mt)
#pragma unroll
        for (int n = 0; n < 8; ++n) {
            int col = n0 + n * 8 + q * 2;
            int rA = m0 + mt * 16 + g;
            int nrA = r0 + rA, nrB = r0 + rA + 8;
            if (nrA < Nn)
                *(uint32_t*)(g_Y1 + (size_t)nrA * 128 + col) = pack2_bf16(acc[mt][n][0], acc[mt][n][1]);
            if (nrB < Nn)
                *(uint32_t*)(g_Y1 + (size_t)nrB * 128 + col) = pack2_bf16(acc[mt][n][2], acc[mt][n][3]);
        }
}

// =============== edge kernel: 2 CTAs/SM, dynamic tiles, 6 barriers/tile (R14) ===============
__global__ __launch_bounds__(ETHREADS, 2)
void edge_kernel(const float* __restrict__ h, const float* __restrict__ eh,
                 const float* __restrict__ be1,
                 const int* __restrict__ src, const int* __restrict__ dst,
                 float* __restrict__ out, int E, int nTiles)
{
    extern __shared__ char smem[];
    const uint32_t sbase = smem_u32(smem);
    const int tid = threadIdx.x;
    const int warp = tid >> 5;
    const int lane = tid & 31;

    // stages A/B: 2 M-strips (64 rows) x 4 N-quarters
    const int mi = warp >> 2;
    const int nj = warp & 3;
    const int m0 = mi * 64;
    const int n0w = nj * 32;   // N=128 (NTH=4)
    // stage C remap: 4 M-strips (32 rows) x 2 N-halves
    const int m0c = (warp & 3) * 32;
    const int n0c = (warp >> 2) * 32;
    const int g = lane >> 2, q = lane & 3;

    float* sB2 = (float*)(smem + SB2_OFF);
    int* sSrc = (int*)(smem + SSRC_OFF);
    int* sDst = (int*)(smem + SDST_OFF);
    int* sTile = (int*)(smem + STILE_OFF);

    if (tid < 128) sB2[tid] = be1[tid];

    // prologue: first ticket + first Wcomb stream
    if (tid == 0) sTile[0] = atomicAdd(&g_ticket, 1);
    cp_w(sbase + WBUF_OFF, IWCB, 34816, tid);
    __syncthreads();
    int tile = sTile[0];

    while (tile < nTiles) {
        const int e0 = tile * M_TILE;

        // idx -> smem (for ym / stage-C preload) + gather with direct broadcast LDG
        if (tid < M_TILE) {
            int eg = e0 + tid; if (eg >= E) eg = E - 1;
            sSrc[tid] = src[eg];
            sDst[tid] = dst[eg];
        }
#pragma unroll
        for (int c = 0; c < 2; ++c) {
            int ss[4], dd[4];
            float4 va[4], vb[4], ve[4];
#pragma unroll
            for (int j = 0; j < 4; ++j) {
                int i = tid + (c * 4 + j) * ETHREADS;
                int e = i >> 4;
                int eg = e0 + e; if (eg >= E) eg = E - 1;
                ss[j] = src[eg]; dd[j] = dst[eg];
            }
#pragma unroll
            for (int j = 0; j < 4; ++j) {
                int i = tid + (c * 4 + j) * ETHREADS;
                int d4 = i & 15;
                int eg = e0 + (i >> 4); if (eg >= E) eg = E - 1;
                va[j] = ((const float4*)(h + (size_t)ss[j] * 64))[d4];
                vb[j] = ((const float4*)(h + (size_t)dd[j] * 64))[d4];
                ve[j] = ((const float4*)(eh + (size_t)eg * 64))[d4];
            }
#pragma unroll
            for (int j = 0; j < 4; ++j) {
                int i = tid + (c * 4 + j) * ETHREADS;
                int e = i >> 4, d4 = i & 15;
                *(uint2*)(smem + SA_OFF + e * STRIDE128 + d4 * 8) =
                    pack4_bf16(va[j].x * vb[j].x, va[j].y * vb[j].y,
                               va[j].z * vb[j].z, va[j].w * vb[j].w);
                *(uint2*)(smem + SA_OFF + e * STRIDE128 + 128 + d4 * 8) =
                    pack4_bf16(ve[j].x, ve[j].y, ve[j].z, ve[j].w);
            }
        }
        CP_WAIT0();
        __syncthreads();   // [3] A + idx + Wcomb ready

        // ---- stage A: x2 = relu(A @ Wcomb + b2) -> SX ----
        {
            float acc[2][2][4][4];
            mma_stage2<8, 4>(sbase + SA_OFF, STRIDE128, sbase + WBUF_OFF, STRIDE128, m0, n0w, lane, acc);
            __syncthreads();   // [4] Wcomb reads done
            cp_w(sbase + WBUF_OFF, IWE2, 34816, tid);   // We2 (overlaps epilogue)
#pragma unroll
            for (int hf = 0; hf < 2; ++hf)
#pragma unroll
                for (int mt = 0; mt < 2; ++mt)
#pragma unroll
                    for (int n = 0; n < 4; ++n) {
                        int col = n0w + n * 8 + q * 2;
                        float b0 = sB2[col], b1 = sB2[col + 1];
                        int rA = m0 + hf * 32 + mt * 16 + g;
                        *(uint32_t*)(smem + SX_OFF + rA * STRIDE128 + col * 2) =
                            pack2_bf16(fmaxf(acc[hf][mt][n][0] + b0, 0.f), fmaxf(acc[hf][mt][n][1] + b1, 0.f));
                        *(uint32_t*)(smem + SX_OFF + (rA + 8) * STRIDE128 + col * 2) =
                            pack2_bf16(fmaxf(acc[hf][mt][n][2] + b0, 0.f), fmaxf(acc[hf][mt][n][3] + b1, 0.f));
                    }
        }
        CP_WAIT0();
        __syncthreads();   // [5] x2 + We2 ready

        // ---- stage B: p = Y1[src] * (x2 @ We2) -> SA (A dead) ----
        {
            uint32_t ym[2][2][4][2];
#pragma unroll
            for (int hf = 0; hf < 2; ++hf)
#pragma unroll
                for (int mt = 0; mt < 2; ++mt)
#pragma unroll
                    for (int n = 0; n < 4; ++n) {
                        int col = n0w + n * 8 + q * 2;
                        int rA = m0 + hf * 32 + mt * 16 + g;
                        ym[hf][mt][n][0] = *(const uint32_t*)(g_Y1 + (size_t)sSrc[rA] * 128 + col);
                        ym[hf][mt][n][1] = *(const uint32_t*)(g_Y1 + (size_t)sSrc[rA + 8] * 128 + col);
                    }
            float acc[2][2][4][4];
            mma_stage2<8, 4>(sbase + SX_OFF, STRIDE128, sbase + WBUF_OFF, STRIDE128, m0, n0w, lane, acc);
            __syncthreads();   // [6] We2/x2 reads done
            cp_w(sbase + WBUF_OFF, IWC, 18432, tid);    // Wc (overlaps epilogue)
            if (tid == 0) sTile[0] = atomicAdd(&g_ticket, 1);   // next tile ticket
#pragma unroll
            for (int hf = 0; hf < 2; ++hf)
#pragma unroll
                for (int mt = 0; mt < 2; ++mt)
#pragma unroll
                    for (int n = 0; n < 4; ++n) {
                        int col = n0w + n * 8 + q * 2;
                        int rA = m0 + hf * 32 + mt * 16 + g;
                        __nv_bfloat162 hA = *(__nv_bfloat162*)&ym[hf][mt][n][0];
                        __nv_bfloat162 hB = *(__nv_bfloat162*)&ym[hf][mt][n][1];
                        *(uint32_t*)(smem + SA_OFF + rA * STRIDE128 + col * 2) =
                            pack2_bf16(acc[hf][mt][n][0] * __bfloat162float(hA.x),
                                       acc[hf][mt][n][1] * __bfloat162float(hA.y));
                        *(uint32_t*)(smem + SA_OFF + (rA + 8) * STRIDE128 + col * 2) =
                            pack2_bf16(acc[hf][mt][n][2] * __bfloat162float(hB.x),
                                       acc[hf][mt][n][3] * __bfloat162float(hB.y));
                    }
        }
        CP_WAIT0();
        __syncthreads();   // [7] p + Wc ready

        // ---- stage C (4Mx2N): m = tanh(p @ Wc); reduce-add to out[dst] ----
        {
            int dReg[2], egReg[2], dRegB[2], egRegB[2];
#pragma unroll
            for (int mt = 0; mt < 2; ++mt) {
                int rA = m0c + mt * 16 + g;
                dReg[mt] = sDst[rA];  egReg[mt] = e0 + rA;
                dRegB[mt] = sDst[rA + 8]; egRegB[mt] = e0 + rA + 8;
            }

            float a6[2][4][4];
            mma_stage<8, 4>(sbase + SA_OFF, STRIDE128, sbase + WBUF_OFF, STRIDE64, m0c, n0c, lane, a6);
            __syncthreads();   // [8] stage C MMA done: SA/WBUF/sSrc/sDst free
            cp_w(sbase + WBUF_OFF, IWCB, 34816, tid);   // NEXT tile's Wcomb (hidden under epilogue+gather)

#pragma unroll
            for (int mt = 0; mt < 2; ++mt) {
#pragma unroll
                for (int n = 0; n < 4; ++n) {
                    int col = n0c + n * 8 + q * 2;
                    if (egReg[mt] < E) {
                        float* p = out + (size_t)dReg[mt] * 64 + col;
                        asm volatile("red.global.add.v2.f32 [%0], {%1,%2};"
                            :: "l"(p), "f"(fast_tanh(a6[mt][n][0])), "f"(fast_tanh(a6[mt][n][1])) : "memory");
                    }
                    if (egRegB[mt] < E) {
                        float* p = out + (size_t)dRegB[mt] * 64 + col;
                        asm volatile("red.global.add.v2.f32 [%0], {%1,%2};"
                            :: "l"(p), "f"(fast_tanh(a6[mt][n][2])), "f"(fast_tanh(a6[mt][n][3])) : "memory");
                    }
                }
            }
        }
        tile = sTile[0];   // written before [7], visible
    }
    CP_WAIT0();   // drain any in-flight weight stream before exit
}

extern "C" void kernel_launch(void* const* d_in, const int* in_sizes, int n_in,
                              void* d_out, int out_size) {
    const float* h   = (const float*)d_in[0];
    const float* eh  = (const float*)d_in[1];
    const float* Wn1 = (const float*)d_in[2];
    const float* bn1 = (const float*)d_in[3];
    const float* Wn2 = (const float*)d_in[4];
    const float* We1 = (const float*)d_in[5];
    const float* be1 = (const float*)d_in[6];
    const float* We2 = (const float*)d_in[7];
    const float* Wc  = (const float*)d_in[8];
    const float* Wue = (const float*)d_in[9];
    const int*   src = (const int*)d_in[10];
    const int*   dst = (const int*)d_in[11];
    float* out = (float*)d_out;

    int E = in_sizes[10];
    int Nn = in_sizes[0] / 64;
    if (Nn > N_MAX) Nn = N_MAX;
    int nTiles = (E + M_TILE - 1) / M_TILE;

    int nNodeBlocks = (Nn + 127) / 128;
    cudaFuncSetAttribute(node_kernel, cudaFuncAttributeMaxDynamicSharedMemorySize, NSMEM_BYTES);
    node_kernel<<<nNodeBlocks + 160, NTHREADS, NSMEM_BYTES>>>(
        h, Wn1, bn1, Wn2, Wue, We1, We2, Wc, out, Nn, nNodeBlocks);

    int nSM = 148;
    cudaDeviceGetAttribute(&nSM, cudaDevAttrMultiProcessorCount, 0);
    int grid = 2 * nSM;
    if (grid > nTiles) grid = nTiles;

    cudaFuncSetAttribute(edge_kernel, cudaFuncAttributeMaxDynamicSharedMemorySize, ESMEM_BYTES);
    edge_kernel<<<grid, ETHREADS, ESMEM_BYTES>>>(h, eh, be1, src, dst, out, E, nTiles);
}